// round 12
// baseline (speedup 1.0000x reference)
#include <cuda_runtime.h>
#include <cuda_fp16.h>
#include <cstdint>

// ---------------- problem constants ----------------
#define BB   8
#define CCH  256
#define HH   64
#define WW   96
#define ND   21
#define NDD  441
#define HW_  6144            // HH*WW

// ---------------- fp16 swizzled parity images ----------------
// image row r in [0,96): parity p = r/48, u = r%48, x = 2u+p.
// element (row r, k-unit ku) at  r*512 + ((ku ^ (r&7))*16) + (k&7)*2
#define IMG_SZ 49152         // 96 rows * 512 B

__device__ __align__(16) unsigned char g_A[(size_t)BB * HH * IMG_SZ];
__device__ __align__(16) unsigned char g_B[(size_t)BB * HH * IMG_SZ];

// ---------------- main-kernel smem (relative to 1024-aligned base) ----------
#define SM_B0   0            // B ring slot 0
#define SM_B1   49152        // B ring slot 1
#define SM_A0   98304        // A image for y0 (resident whole kernel)
#define SM_A1   147456       // A image for y1
#define SMEM_REQ (196608 + 1024)

// ---------------- ptx helpers (baseline PTX only) -------
__device__ __forceinline__ void cp_async16(uint32_t s, const void* g) {
    asm volatile("cp.async.cg.shared.global [%0], [%1], 16;\n" :: "r"(s), "l"(g));
}
__device__ __forceinline__ void cp_commit() {
    asm volatile("cp.async.commit_group;" ::: "memory");
}
template<int N> __device__ __forceinline__ void cp_wait() {
    asm volatile("cp.async.wait_group %0;" :: "n"(N) : "memory");
}
__device__ __forceinline__ void ldsm4(uint32_t* r, uint32_t a) {
    asm volatile("ldmatrix.sync.aligned.m8n8.x4.shared.b16 {%0,%1,%2,%3}, [%4];"
                 : "=r"(r[0]), "=r"(r[1]), "=r"(r[2]), "=r"(r[3]) : "r"(a));
}
__device__ __forceinline__ void mma16816(float* d, const uint32_t* a, const uint32_t* b) {
    asm volatile("mma.sync.aligned.m16n8k16.row.col.f32.f16.f16.f32 "
                 "{%0,%1,%2,%3}, {%4,%5,%6,%7}, {%8,%9}, {%0,%1,%2,%3};"
                 : "+f"(d[0]), "+f"(d[1]), "+f"(d[2]), "+f"(d[3])
                 : "r"(a[0]), "r"(a[1]), "r"(a[2]), "r"(a[3]), "r"(b[0]), "r"(b[1]));
}

// ================= prepass: parity-split fp16 swizzled image of one row =====
// Identical transform for A (in1) and B (in2): row r -> x = 2*(r%48) + r/48.
__global__ __launch_bounds__(256) void prep_img(const float* __restrict__ in1,
                                                const float* __restrict__ in2) {
    __shared__ float raw[64][97];
    int bid = blockIdx.x;
    bool isB = bid >= (BB * HH);
    int sb = isB ? bid - BB * HH : bid;
    int y = sb & 63, b = sb >> 6;
    int tid = threadIdx.x, w = tid >> 5, lane = tid & 31;
    const float* src_t = isB ? in2 : in1;
    unsigned char* img = (isB ? g_B : g_A) + (size_t)sb * IMG_SZ;

    for (int q = 0; q < 4; q++) {
        __syncthreads();
        #pragma unroll
        for (int rr = 0; rr < 8; rr++) {
            int c = w * 8 + rr;
            const float* src = src_t + (((size_t)b * CCH + q * 64 + c) * HH + y) * WW;
            #pragma unroll
            for (int m = 0; m < 3; m++)
                raw[c][lane + 32 * m] = src[lane + 32 * m];
        }
        __syncthreads();
        #pragma unroll
        for (int it = 0; it < 3; it++) {
            int u = tid + it * 256;              // u < 768: 96 rows * 8 k-units
            int r = u >> 3, kl = u & 7;
            int ku = q * 8 + kl;
            int x = (r < 48) ? (2 * r) : (2 * r - 95);   // parity-split mapping
            uint32_t h[4];
            #pragma unroll
            for (int j = 0; j < 4; j++) {
                __half2 v = __floats2half2_rn(raw[kl * 8 + 2 * j][x],
                                              raw[kl * 8 + 2 * j + 1][x]);
                h[j] = *reinterpret_cast<uint32_t*>(&v);
            }
            int off = r * 512 + ((ku ^ (r & 7)) << 4);
            *reinterpret_cast<uint4*>(img + off) = make_uint4(h[0], h[1], h[2], h[3]);
        }
    }
}

// ================= main kernel ================================================
// Block = (b, y-pair (y0, y0+2) same parity). 12 warps = 2 y-rows x 2 parities
// x 3 m16 tiles; each warp full K=256, A fragments in registers. One staged B
// row serves dy=i for y0 and dy=i-1 for y1. 2-slot B ring, A resident in smem.
__global__ __launch_bounds__(384) void corr_hmma(float* __restrict__ out) {
    extern __shared__ __align__(16) unsigned char smraw[];
    uint32_t SB = ((uint32_t)__cvta_generic_to_shared(smraw) + 1023u) & ~1023u;

    int bid = blockIdx.x;
    int p = bid & 31, b = bid >> 5;
    int y0 = (p >> 1) * 4 + (p & 1);
    int y1 = y0 + 2;
    int tid = threadIdx.x, w = tid >> 5, lane = tid & 31;
    int yr  = w / 6;         // output row: 0 -> y0, 1 -> y1
    int wl  = w % 6;
    int par = wl / 3;        // parity (0: x even, 1: x odd)
    int mt  = wl % 3;        // m16 tile within parity
    int lg = lane >> 2, t = lane & 3;
    int l7 = lane & 7;
    int yo = yr ? y1 : y0;

    // ---- valid B-row list: i in 0..21, y2 = y0-20+2i ----
    int vlist[22]; int nv = 0;
    #pragma unroll
    for (int i = 0; i < 22; i++) {
        int y2 = y0 - 20 + 2 * i;
        if ((unsigned)y2 < (unsigned)HH) vlist[nv++] = i;
    }

    // ---- staging: 96-row B image -> ring slot idx&1 (384 thr, 8 units each) --
    auto stage = [&](int idx) {
        int y2 = y0 - 20 + 2 * vlist[idx];
        const unsigned char* src = g_B + (size_t)(b * HH + y2) * IMG_SZ;
        uint32_t dst = SB + (uint32_t)((idx & 1) * 49152);
        #pragma unroll
        for (int it = 0; it < 8; it++) {
            int i = tid + it * 384;              // i < 3072
            cp_async16(dst + (uint32_t)(i * 16), src + (size_t)i * 16);
        }
    };

    // ---- prologue: both A images + stage(0) (G0), stage(1) (G1) ----
    {
        const unsigned char* imgA0 = g_A + (size_t)(b * HH + y0) * IMG_SZ;
        const unsigned char* imgA1 = g_A + (size_t)(b * HH + y1) * IMG_SZ;
        #pragma unroll
        for (int it = 0; it < 8; it++) {
            int i = tid + it * 384;
            cp_async16(SB + SM_A0 + (uint32_t)(i * 16), imgA0 + (size_t)i * 16);
        }
        #pragma unroll
        for (int it = 0; it < 8; it++) {
            int i = tid + it * 384;
            cp_async16(SB + SM_A1 + (uint32_t)(i * 16), imgA1 + (size_t)i * 16);
        }
        stage(0);
        cp_commit();                             // G0 = A0 + A1 + B(0)
        if (nv > 1) stage(1);
        cp_commit();                             // G1 = B(1)
    }

    // ---- zero invalid-dy output slices for both outputs (overlaps cp.async) --
    #pragma unroll 1
    for (int z = 0; z < 2; z++) {
        int yz = z ? y1 : y0;
        #pragma unroll 1
        for (int d = 0; d < ND; d++) {
            int y2 = yz - 20 + 2 * d;
            if ((unsigned)y2 >= (unsigned)HH) {
                for (int i = tid; i < ND * WW; i += 384) {
                    int dj = i / WW, x = i - dj * WW;
                    out[(((size_t)b * NDD + d * ND + dj) * HH + yz) * WW + x] = 0.0f;
                }
            }
        }
    }

    // ---- A + B(0) resident -> hoist this warp's A fragments (full K=256) ----
    cp_wait<1>();
    __syncthreads();
    uint32_t a[16][4];
    {
        uint32_t arow = (uint32_t)(48 * par + 16 * mt) + (uint32_t)l7 + 8u * ((lane >> 3) & 1);
        uint32_t abase = SB + (yr ? SM_A1 : SM_A0) + arow * 512u;
        #pragma unroll
        for (int ks = 0; ks < 16; ks++) {
            uint32_t aku = (uint32_t)(2 * ks) + (uint32_t)(lane >> 4);
            ldsm4(a[ks], abase + ((aku ^ (uint32_t)l7) << 4));
        }
    }
    // A region never rewritten -> no barrier needed after hoist

    // ---- B ldsm row offsets: q = 0..2 covers tiles jj = 2q, 2q+1 ----
    // valid pairs: mt=0 -> q 1..2, mt=1 -> q 0..2, mt=2 -> q 0..1
    int qlo = (mt == 0) ? 1 : 0;
    int qhi = (mt == 2) ? 1 : 2;
    int boff[3];
    #pragma unroll
    for (int q = 0; q < 3; q++) {
        int row = 48 * par + 8 * (2 * mt + 2 * q + (lane >> 4)) - 16 + l7;
        boff[q] = row * 512;
    }
    uint32_t kadd = (uint32_t)((lane >> 3) & 1);
    const float scale = 1.0f / 256.0f;

    // ---- pipeline over shared B rows ----
    #pragma unroll 1
    for (int idx = 0; idx < nv; idx++) {
        if (idx + 1 < nv) cp_wait<1>(); else cp_wait<0>();
        __syncthreads();                         // staged B(idx) visible to all

        int vi = vlist[idx];
        bool valid = yr ? (vi >= 1) : (vi <= 20);
        int d_mine = yr ? (vi - 1) : vi;
        uint32_t slot = SB + (uint32_t)((idx & 1) * 49152);

        float acc[6][4];
        #pragma unroll
        for (int jj = 0; jj < 6; jj++)
            #pragma unroll
            for (int r = 0; r < 4; r++) acc[jj][r] = 0.0f;

        if (valid) {
            #pragma unroll
            for (int ks = 0; ks < 16; ks++) {
                uint32_t sw = (((uint32_t)(2 * ks) + kadd) ^ (uint32_t)l7) << 4;
                #pragma unroll
                for (int q = 0; q < 3; q++) {
                    if (q >= qlo && q <= qhi) {
                        uint32_t bfr[2][2];
                        ldsm4(&bfr[0][0], slot + (uint32_t)boff[q] + sw);
                        mma16816(acc[2 * q],     a[ks], bfr[0]);
                        mma16816(acc[2 * q + 1], a[ks], bfr[1]);
                    }
                }
            }
        }

        __syncthreads();                         // all readers done with slot
        if (idx + 2 < nv) { stage(idx + 2); cp_commit(); }

        // ---- epilogue from registers (overlaps next stage) ----
        if (valid) {
            size_t obase = ((size_t)(b * NDD + d_mine * ND)) * HW_ + (size_t)yo * WW;
            #pragma unroll
            for (int jj = 0; jj < 6; jj++) {
                #pragma unroll
                for (int r = 0; r < 4; r++) {
                    int rh = r >> 1;
                    int dxj = 8 * jj + 2 * t + (r & 1) - lg - 8 * rh - 6;
                    int x = 32 * mt + 2 * lg + 16 * rh + par;
                    if ((unsigned)dxj <= 20u)
                        out[obase + (size_t)dxj * HW_ + x] = acc[jj][r] * scale;
                }
            }
        }
    }
}

// ================= launch =================
extern "C" void kernel_launch(void* const* d_in, const int* in_sizes, int n_in,
                              void* d_out, int out_size)
{
    const float* in1 = (const float*)d_in[0];
    const float* in2 = (const float*)d_in[1];
    float* out = (float*)d_out;

    cudaFuncSetAttribute(corr_hmma, cudaFuncAttributeMaxDynamicSharedMemorySize, SMEM_REQ);

    prep_img<<<2 * BB * HH, 256>>>(in1, in2);
    corr_hmma<<<BB * (HH / 2), 384, SMEM_REQ>>>(out);
}

// round 13
// speedup vs baseline: 1.1808x; 1.1808x over previous
#include <cuda_runtime.h>
#include <cuda_fp16.h>
#include <cstdint>

// ---------------- problem constants ----------------
#define BB   8
#define CCH  256
#define HH   64
#define WW   96
#define ND   21
#define NDD  441
#define HW_  6144            // HH*WW

// ---------------- fp16 swizzled parity images ----------------
// image row r in [0,96): parity p = r/48, u = r%48, x = 2u+p.
// element (row r, k-unit ku) at  r*512 + ((ku ^ (r&7))*16) + (k&7)*2
#define IMG_SZ 49152         // 96 rows * 512 B; parity half = 24576 B contiguous

__device__ __align__(16) unsigned char g_A[(size_t)BB * HH * IMG_SZ];
__device__ __align__(16) unsigned char g_B[(size_t)BB * HH * IMG_SZ];

// ---------------- main-kernel smem (relative to 1024-aligned base) ----------
#define HALF_SZ 24576
#define SM_A    0            // A parity half; becomes split-K scratch after hoist
#define SM_B0   24576        // B ring slot 0 (parity half)
#define SM_B1   49152        // B ring slot 1
#define SMEM_REQ (73728 + 1024)

// ---------------- ptx helpers (baseline PTX only) -------
__device__ __forceinline__ void cp_async16(uint32_t s, const void* g) {
    asm volatile("cp.async.cg.shared.global [%0], [%1], 16;\n" :: "r"(s), "l"(g));
}
__device__ __forceinline__ void cp_commit() {
    asm volatile("cp.async.commit_group;" ::: "memory");
}
template<int N> __device__ __forceinline__ void cp_wait() {
    asm volatile("cp.async.wait_group %0;" :: "n"(N) : "memory");
}
__device__ __forceinline__ void ldsm4(uint32_t* r, uint32_t a) {
    asm volatile("ldmatrix.sync.aligned.m8n8.x4.shared.b16 {%0,%1,%2,%3}, [%4];"
                 : "=r"(r[0]), "=r"(r[1]), "=r"(r[2]), "=r"(r[3]) : "r"(a));
}
__device__ __forceinline__ void mma16816(float* d, const uint32_t* a, const uint32_t* b) {
    asm volatile("mma.sync.aligned.m16n8k16.row.col.f32.f16.f16.f32 "
                 "{%0,%1,%2,%3}, {%4,%5,%6,%7}, {%8,%9}, {%0,%1,%2,%3};"
                 : "+f"(d[0]), "+f"(d[1]), "+f"(d[2]), "+f"(d[3])
                 : "r"(a[0]), "r"(a[1]), "r"(a[2]), "r"(a[3]), "r"(b[0]), "r"(b[1]));
}

// ================= prepass: parity-split fp16 swizzled image of one row =====
// Identical transform for A (in1) and B (in2): row r -> x = 2*(r%48) + r/48.
__global__ __launch_bounds__(256) void prep_img(const float* __restrict__ in1,
                                                const float* __restrict__ in2) {
    __shared__ float raw[64][97];
    int bid = blockIdx.x;
    bool isB = bid >= (BB * HH);
    int sb = isB ? bid - BB * HH : bid;
    int y = sb & 63, b = sb >> 6;
    int tid = threadIdx.x, w = tid >> 5, lane = tid & 31;
    const float* src_t = isB ? in2 : in1;
    unsigned char* img = (isB ? g_B : g_A) + (size_t)sb * IMG_SZ;

    for (int q = 0; q < 4; q++) {
        __syncthreads();
        #pragma unroll
        for (int rr = 0; rr < 8; rr++) {
            int c = w * 8 + rr;
            const float* src = src_t + (((size_t)b * CCH + q * 64 + c) * HH + y) * WW;
            #pragma unroll
            for (int m = 0; m < 3; m++)
                raw[c][lane + 32 * m] = src[lane + 32 * m];
        }
        __syncthreads();
        #pragma unroll
        for (int it = 0; it < 3; it++) {
            int u = tid + it * 256;              // u < 768: 96 rows * 8 k-units
            int r = u >> 3, kl = u & 7;
            int ku = q * 8 + kl;
            int x = (r < 48) ? (2 * r) : (2 * r - 95);   // parity-split mapping
            uint32_t h[4];
            #pragma unroll
            for (int j = 0; j < 4; j++) {
                __half2 v = __floats2half2_rn(raw[kl * 8 + 2 * j][x],
                                              raw[kl * 8 + 2 * j + 1][x]);
                h[j] = *reinterpret_cast<uint32_t*>(&v);
            }
            int off = r * 512 + ((ku ^ (r & 7)) << 4);
            *reinterpret_cast<uint4*>(img + off) = make_uint4(h[0], h[1], h[2], h[3]);
        }
    }
}

// ================= main kernel ================================================
// Block = (b, y, parity). 6 warps = 3 m16 tiles x 2 k-halves; split-K reduce
// through a small smem scratch overlaying the A half after register hoist.
// Small smem (73 KB) + modest regs -> 2-3 co-resident CTAs/SM hide the
// per-iteration latency chain that bound all 1-CTA variants.
__global__ __launch_bounds__(192, 2) void corr_hmma(float* __restrict__ out) {
    extern __shared__ __align__(16) unsigned char smraw[];
    uint32_t SB = ((uint32_t)__cvta_generic_to_shared(smraw) + 1023u) & ~1023u;

    int bid = blockIdx.x;
    int par = bid & 1;
    int y = (bid >> 1) & 63;
    int b = bid >> 7;
    int tid = threadIdx.x, w = tid >> 5, lane = tid & 31;
    int mt = w % 3;          // m16 tile within parity half
    int kh = w / 3;          // k-half: k-units kh*16 .. kh*16+15
    int lg = lane >> 2, t = lane & 3;
    int l7 = lane & 7;

    // ---- valid dy list ----
    int vlist[ND]; int nv = 0;
    #pragma unroll
    for (int d = 0; d < ND; d++) {
        int y2 = y - 20 + 2 * d;
        if ((unsigned)y2 < (unsigned)HH) vlist[nv++] = d;
    }

    // ---- staging: B parity half (24 KB) -> ring slot idx&1 ----
    auto stage = [&](int idx) {
        int y2 = y - 20 + 2 * vlist[idx];
        const unsigned char* src = g_B + (size_t)(b * HH + y2) * IMG_SZ
                                 + (size_t)(par * HALF_SZ);
        uint32_t dst = SB + (uint32_t)(((idx & 1) + 1) * HALF_SZ);
        #pragma unroll
        for (int it = 0; it < 8; it++) {
            int i = tid + it * 192;              // i < 1536
            cp_async16(dst + (uint32_t)(i * 16), src + (size_t)i * 16);
        }
    };

    // ---- prologue: A half + B(0) (G0), B(1) (G1) ----
    {
        const unsigned char* srcA = g_A + (size_t)(b * HH + y) * IMG_SZ
                                  + (size_t)(par * HALF_SZ);
        #pragma unroll
        for (int it = 0; it < 8; it++) {
            int i = tid + it * 192;
            cp_async16(SB + SM_A + (uint32_t)(i * 16), srcA + (size_t)i * 16);
        }
        stage(0);
        cp_commit();                             // G0 = A + B(0)
        if (nv > 1) stage(1);
        cp_commit();                             // G1 = B(1)
    }

    // ---- zero invalid-dy output slices (this parity's x positions only) ----
    #pragma unroll 1
    for (int d = 0; d < ND; d++) {
        int y2 = y - 20 + 2 * d;
        if ((unsigned)y2 >= (unsigned)HH) {
            for (int i = tid; i < ND * 48; i += 192) {
                int dj = i / 48, xh = i - dj * 48;
                out[(((size_t)b * NDD + d * ND + dj) * HH + y) * WW + 2 * xh + par] = 0.0f;
            }
        }
    }

    // ---- A half resident -> hoist this warp's fragments (K half) ----
    cp_wait<1>();
    __syncthreads();
    uint32_t a[8][4];
    {
        uint32_t arow = (uint32_t)(16 * mt) + (uint32_t)l7 + 8u * ((lane >> 3) & 1);
        uint32_t abase = SB + SM_A + arow * 512u;
        #pragma unroll
        for (int ks = 0; ks < 8; ks++) {
            uint32_t aku = (uint32_t)(kh * 16 + 2 * ks) + (uint32_t)(lane >> 4);
            ldsm4(a[ks], abase + ((aku ^ (uint32_t)l7) << 4));
        }
    }
    __syncthreads();          // hoists done -> A region becomes reduce scratch

    // ---- B ldsm local row offsets: q covers tiles jj = 2q, 2q+1 ----
    // valid pairs: mt=0 -> q 1..2, mt=1 -> q 0..2, mt=2 -> q 0..1
    int qlo = (mt == 0) ? 1 : 0;
    int qhi = (mt == 2) ? 1 : 2;
    int boff[3];
    #pragma unroll
    for (int q = 0; q < 3; q++) {
        int row = 8 * (2 * mt + 2 * q + (lane >> 4)) - 16 + l7;
        if (q < qlo || q > qhi) row = 0;         // unused; keep address sane
        boff[q] = row * 512;
    }
    uint32_t kadd = (uint32_t)((lane >> 3) & 1);
    uint32_t redslot = SB + SM_A + (uint32_t)(mt * 3072);   // 24 regs * 32 lanes * 4B
    const float scale = 1.0f / 256.0f;

    // ---- pipeline over valid dy rows ----
    #pragma unroll 1
    for (int idx = 0; idx < nv; idx++) {
        if (idx + 1 < nv) cp_wait<1>(); else cp_wait<0>();
        __syncthreads();                         // B(idx) visible

        uint32_t slot = SB + (uint32_t)(((idx & 1) + 1) * HALF_SZ);

        float acc[6][4];
        #pragma unroll
        for (int jj = 0; jj < 6; jj++)
            #pragma unroll
            for (int r = 0; r < 4; r++) acc[jj][r] = 0.0f;

        #pragma unroll
        for (int ks = 0; ks < 8; ks++) {
            uint32_t sw = (((uint32_t)(kh * 16 + 2 * ks) + kadd) ^ (uint32_t)l7) << 4;
            #pragma unroll
            for (int q = 0; q < 3; q++) {
                if (q >= qlo && q <= qhi) {
                    uint32_t bfr[2][2];
                    ldsm4(&bfr[0][0], slot + (uint32_t)boff[q] + sw);
                    mma16816(acc[2 * q],     a[ks], bfr[0]);
                    mma16816(acc[2 * q + 1], a[ks], bfr[1]);
                }
            }
        }

        // kh=0 publishes partials; barrier also proves all B(idx) reads done
        if (kh == 0) {
            #pragma unroll
            for (int jj = 0; jj < 6; jj++)
                #pragma unroll
                for (int r = 0; r < 4; r++)
                    asm volatile("st.shared.f32 [%0], %1;"
                        :: "r"(redslot + (uint32_t)(((jj * 4 + r) * 32 + lane) * 4)),
                           "f"(acc[jj][r]) : "memory");
        }
        __syncthreads();
        if (idx + 2 < nv) { stage(idx + 2); cp_commit(); }

        // kh=1 reduces + writes the band (overlaps staging)
        if (kh == 1) {
            int dyi = vlist[idx];
            size_t obase = ((size_t)(b * NDD + dyi * ND)) * HW_ + (size_t)y * WW;
            #pragma unroll
            for (int jj = 0; jj < 6; jj++) {
                #pragma unroll
                for (int r = 0; r < 4; r++) {
                    float p;
                    asm volatile("ld.shared.f32 %0, [%1];"
                        : "=f"(p)
                        : "r"(redslot + (uint32_t)(((jj * 4 + r) * 32 + lane) * 4)));
                    acc[jj][r] += p;
                    int rh = r >> 1;
                    int dxj = 8 * jj + 2 * t + (r & 1) - lg - 8 * rh - 6;
                    int x = 32 * mt + 2 * lg + 16 * rh + par;
                    if ((unsigned)dxj <= 20u)
                        out[obase + (size_t)dxj * HW_ + x] = acc[jj][r] * scale;
                }
            }
        }
    }
}

// ================= launch =================
extern "C" void kernel_launch(void* const* d_in, const int* in_sizes, int n_in,
                              void* d_out, int out_size)
{
    const float* in1 = (const float*)d_in[0];
    const float* in2 = (const float*)d_in[1];
    float* out = (float*)d_out;

    cudaFuncSetAttribute(corr_hmma, cudaFuncAttributeMaxDynamicSharedMemorySize, SMEM_REQ);

    prep_img<<<2 * BB * HH, 256>>>(in1, in2);
    corr_hmma<<<BB * HH * 2, 192, SMEM_REQ>>>(out);
}

// round 14
// speedup vs baseline: 1.3063x; 1.1063x over previous
#include <cuda_runtime.h>
#include <cuda_fp16.h>
#include <cstdint>

// ---------------- problem constants ----------------
#define BB   8
#define CCH  256
#define HH   64
#define WW   96
#define ND   21
#define NDD  441
#define HW_  6144            // HH*WW

// ---------------- fp16 swizzled parity images ----------------
// image row r in [0,96): parity p = r/48, u = r%48, x = 2u+p.
// element (row r, k-unit ku) at  r*512 + ((ku ^ (r&7))*16) + (k&7)*2
#define IMG_SZ 49152         // 96 rows * 512 B; parity half = 24576 B contiguous

__device__ __align__(16) unsigned char g_A[(size_t)BB * HH * IMG_SZ];
__device__ __align__(16) unsigned char g_B[(size_t)BB * HH * IMG_SZ];

// ---------------- main-kernel smem (relative to 1024-aligned base) ----------
#define HALF_SZ 24576
#define SM_A    0            // A parity half; becomes split-K scratch after hoist
#define SMEM_REQ (73728 + 1024)

// ---------------- ptx helpers (baseline PTX only) -------
__device__ __forceinline__ void cp_async16(uint32_t s, const void* g) {
    asm volatile("cp.async.cg.shared.global [%0], [%1], 16;\n" :: "r"(s), "l"(g));
}
__device__ __forceinline__ void cp_commit() {
    asm volatile("cp.async.commit_group;" ::: "memory");
}
template<int N> __device__ __forceinline__ void cp_wait() {
    asm volatile("cp.async.wait_group %0;" :: "n"(N) : "memory");
}
__device__ __forceinline__ void ldsm4(uint32_t* r, uint32_t a) {
    asm volatile("ldmatrix.sync.aligned.m8n8.x4.shared.b16 {%0,%1,%2,%3}, [%4];"
                 : "=r"(r[0]), "=r"(r[1]), "=r"(r[2]), "=r"(r[3]) : "r"(a));
}
__device__ __forceinline__ void mma16816(float* d, const uint32_t* a, const uint32_t* b) {
    asm volatile("mma.sync.aligned.m16n8k16.row.col.f32.f16.f16.f32 "
                 "{%0,%1,%2,%3}, {%4,%5,%6,%7}, {%8,%9}, {%0,%1,%2,%3};"
                 : "+f"(d[0]), "+f"(d[1]), "+f"(d[2]), "+f"(d[3])
                 : "r"(a[0]), "r"(a[1]), "r"(a[2]), "r"(a[3]), "r"(b[0]), "r"(b[1]));
}

// ================= prepass: one (tensor, row, k-chunk) per block =============
// Identical transform for A (in1) and B (in2): row r -> x = 2*(r%48) + r/48.
__global__ __launch_bounds__(256) void prep_img(const float* __restrict__ in1,
                                                const float* __restrict__ in2) {
    __shared__ float raw[64][97];
    int bid = blockIdx.x;
    int q = bid & 3;                 // k-chunk: channels q*64..q*64+63
    int sb = (bid >> 2) & 511;       // (b, y)
    bool isB = bid >= 2048;
    int y = sb & 63, b = sb >> 6;
    int tid = threadIdx.x, w = tid >> 5, lane = tid & 31;
    const float* src_t = isB ? in2 : in1;
    unsigned char* img = (isB ? g_B : g_A) + (size_t)sb * IMG_SZ;

    #pragma unroll
    for (int rr = 0; rr < 8; rr++) {
        int c = w * 8 + rr;
        const float* src = src_t + (((size_t)b * CCH + q * 64 + c) * HH + y) * WW;
        #pragma unroll
        for (int m = 0; m < 3; m++)
            raw[c][lane + 32 * m] = src[lane + 32 * m];
    }
    __syncthreads();
    #pragma unroll
    for (int it = 0; it < 3; it++) {
        int u = tid + it * 256;              // u < 768: 96 rows * 8 k-units
        int r = u >> 3, kl = u & 7;
        int ku = q * 8 + kl;
        int x = (r < 48) ? (2 * r) : (2 * r - 95);   // parity-split mapping
        uint32_t h[4];
        #pragma unroll
        for (int j = 0; j < 4; j++) {
            __half2 v = __floats2half2_rn(raw[kl * 8 + 2 * j][x],
                                          raw[kl * 8 + 2 * j + 1][x]);
            h[j] = *reinterpret_cast<uint32_t*>(&v);
        }
        int off = r * 512 + ((ku ^ (r & 7)) << 4);
        *reinterpret_cast<uint4*>(img + off) = make_uint4(h[0], h[1], h[2], h[3]);
    }
}

// ================= main kernel ================================================
// Block = (b, y, parity). 6 warps = 3 m16 tiles x 2 k-halves; split-K reduce
// through a small smem scratch overlaying the A half after register hoist.
// 73.7 KB smem + <=113 regs -> 3 co-resident CTAs/SM (18 warps).
__global__ __launch_bounds__(192, 3) void corr_hmma(float* __restrict__ out) {
    extern __shared__ __align__(16) unsigned char smraw[];
    uint32_t SB = ((uint32_t)__cvta_generic_to_shared(smraw) + 1023u) & ~1023u;

    int bid = blockIdx.x;
    int par = bid & 1;
    int y = (bid >> 1) & 63;
    int b = bid >> 7;
    int tid = threadIdx.x, w = tid >> 5, lane = tid & 31;
    int mt = w % 3;          // m16 tile within parity half
    int kh = w / 3;          // k-half: k-units kh*16 .. kh*16+15
    int lg = lane >> 2, t = lane & 3;
    int l7 = lane & 7;

    // ---- staging: B parity half (24 KB) -> ring slot d&1 (empty if invalid) --
    auto stage = [&](int d) {
        int y2 = y - 20 + 2 * d;
        if ((unsigned)y2 < (unsigned)HH) {
            const unsigned char* src = g_B + (size_t)(b * HH + y2) * IMG_SZ
                                     + (size_t)(par * HALF_SZ);
            uint32_t dst = SB + (uint32_t)(((d & 1) + 1) * HALF_SZ);
            #pragma unroll
            for (int it = 0; it < 8; it++) {
                int i = tid + it * 192;          // i < 1536
                cp_async16(dst + (uint32_t)(i * 16), src + (size_t)i * 16);
            }
        }
    };

    // ---- prologue: A half + B(0) (G0), B(1) (G1) ----
    {
        const unsigned char* srcA = g_A + (size_t)(b * HH + y) * IMG_SZ
                                  + (size_t)(par * HALF_SZ);
        #pragma unroll
        for (int it = 0; it < 8; it++) {
            int i = tid + it * 192;
            cp_async16(SB + SM_A + (uint32_t)(i * 16), srcA + (size_t)i * 16);
        }
        stage(0);
        cp_commit();                             // G0 = A + B(0)
        stage(1);
        cp_commit();                             // G1 = B(1)
    }

    // ---- zero invalid-dy output slices (this parity's x positions only) ----
    #pragma unroll 1
    for (int d = 0; d < ND; d++) {
        int y2 = y - 20 + 2 * d;
        if ((unsigned)y2 >= (unsigned)HH) {
            for (int i = tid; i < ND * 48; i += 192) {
                int dj = i / 48, xh = i - dj * 48;
                out[(((size_t)b * NDD + d * ND + dj) * HH + y) * WW + 2 * xh + par] = 0.0f;
            }
        }
    }

    // ---- A half resident -> hoist this warp's fragments (K half) ----
    cp_wait<1>();
    __syncthreads();
    uint32_t a[8][4];
    {
        uint32_t arow = (uint32_t)(16 * mt) + (uint32_t)l7 + 8u * ((lane >> 3) & 1);
        uint32_t abase = SB + SM_A + arow * 512u;
        #pragma unroll
        for (int ks = 0; ks < 8; ks++) {
            uint32_t aku = (uint32_t)(kh * 16 + 2 * ks) + (uint32_t)(lane >> 4);
            ldsm4(a[ks], abase + ((aku ^ (uint32_t)l7) << 4));
        }
    }
    __syncthreads();          // hoists done -> A region becomes reduce scratch

    // ---- B ldsm local row offsets: q covers tiles jj = 2q, 2q+1 ----
    // valid pairs: mt=0 -> q 1..2, mt=1 -> q 0..2, mt=2 -> q 0..1
    int qlo = (mt == 0) ? 1 : 0;
    int qhi = (mt == 2) ? 1 : 2;
    int boff[3];
    #pragma unroll
    for (int q = 0; q < 3; q++) {
        int row = 8 * (2 * mt + 2 * q + (lane >> 4)) - 16 + l7;
        if (q < qlo || q > qhi) row = 0;         // unused; keep address sane
        boff[q] = row * 512;
    }
    uint32_t kadd = (uint32_t)((lane >> 3) & 1);
    uint32_t redslot = SB + SM_A + (uint32_t)(mt * 3072);   // 24 regs * 32 lanes * 4B
    const float scale = 1.0f / 256.0f;

    // ---- pipeline over all 21 dy (invalid iters: barriers only) ----
    #pragma unroll 1
    for (int d = 0; d < ND; d++) {
        cp_wait<1>();
        __syncthreads();                         // B(d) visible (if valid)

        bool valid = (unsigned)(y - 20 + 2 * d) < (unsigned)HH;
        uint32_t slot = SB + (uint32_t)(((d & 1) + 1) * HALF_SZ);

        float acc[6][4];
        #pragma unroll
        for (int jj = 0; jj < 6; jj++)
            #pragma unroll
            for (int r = 0; r < 4; r++) acc[jj][r] = 0.0f;

        if (valid) {
            #pragma unroll
            for (int ks = 0; ks < 8; ks++) {
                uint32_t sw = (((uint32_t)(kh * 16 + 2 * ks) + kadd) ^ (uint32_t)l7) << 4;
                #pragma unroll
                for (int q = 0; q < 3; q++) {
                    if (q >= qlo && q <= qhi) {
                        uint32_t bfr[2][2];
                        ldsm4(&bfr[0][0], slot + (uint32_t)boff[q] + sw);
                        mma16816(acc[2 * q],     a[ks], bfr[0]);
                        mma16816(acc[2 * q + 1], a[ks], bfr[1]);
                    }
                }
            }
            // kh=0 publishes partials
            if (kh == 0) {
                #pragma unroll
                for (int jj = 0; jj < 6; jj++)
                    #pragma unroll
                    for (int r = 0; r < 4; r++)
                        asm volatile("st.shared.f32 [%0], %1;"
                            :: "r"(redslot + (uint32_t)(((jj * 4 + r) * 32 + lane) * 4)),
                               "f"(acc[jj][r]) : "memory");
            }
        }
        __syncthreads();                         // partials visible; B reads done
        if (d + 2 < ND) stage(d + 2);
        cp_commit();                             // group per iteration, maybe empty

        // kh=1 reduces + writes the band (overlaps staging)
        if (valid && kh == 1) {
            size_t obase = ((size_t)(b * NDD + d * ND)) * HW_ + (size_t)y * WW;
            #pragma unroll
            for (int jj = 0; jj < 6; jj++) {
                #pragma unroll
                for (int r = 0; r < 4; r++) {
                    float p;
                    asm volatile("ld.shared.f32 %0, [%1];"
                        : "=f"(p)
                        : "r"(redslot + (uint32_t)(((jj * 4 + r) * 32 + lane) * 4)));
                    acc[jj][r] += p;
                    int rh = r >> 1;
                    int dxj = 8 * jj + 2 * t + (r & 1) - lg - 8 * rh - 6;
                    int x = 32 * mt + 2 * lg + 16 * rh + par;
                    if ((unsigned)dxj <= 20u)
                        out[obase + (size_t)dxj * HW_ + x] = acc[jj][r] * scale;
                }
            }
        }
    }
}

// ================= launch =================
extern "C" void kernel_launch(void* const* d_in, const int* in_sizes, int n_in,
                              void* d_out, int out_size)
{
    const float* in1 = (const float*)d_in[0];
    const float* in2 = (const float*)d_in[1];
    float* out = (float*)d_out;

    cudaFuncSetAttribute(corr_hmma, cudaFuncAttributeMaxDynamicSharedMemorySize, SMEM_REQ);

    prep_img<<<4096, 256>>>(in1, in2);
    corr_hmma<<<BB * HH * 2, 192, SMEM_REQ>>>(out);
}